// round 6
// baseline (speedup 1.0000x reference)
#include <cuda_runtime.h>
#include <cuda_bf16.h>
#include <math.h>

// Problem constants (fixed by the dataset)
#define NN 500000
#define EE 8000000
#define IN_DIM 128
#define H1 32
#define H2 16
#define SCAN_BLK 1024
#define NB_SCAN ((NN + SCAN_BLK - 1) / SCAN_BLK)   // 489

// Scratch (device globals; no cudaMalloc allowed)
__device__ float g_A[NN * H1];        // y1 = (x@W1)*dinv
__device__ float g_B[NN * H1];        // h1 = relu(agg1*dinv + b1)
__device__ float g_C[NN * H2];        // y2 = (h1@W2)*dinv
__device__ int   g_eidx[EE];          // CSR: src ids grouped by dst
__device__ int   g_cnt[NN];           // edge in-degree (no self loop)
__device__ int   g_cur[NN];           // fill cursors
__device__ int   g_scan[NN];          // per-block inclusive scan of cnt
__device__ int   g_bsum[NB_SCAN];     // block totals
__device__ int   g_boff[NB_SCAN];     // exclusive scan of block totals
__device__ int   g_rowstart[NN + 1];
__device__ float g_dinv[NN];

// ---------------- packed f32x2 helpers --------------------------------------

union F2U { unsigned long long u; float2 f; };

__device__ __forceinline__ unsigned long long pack_dup(float x) {
    unsigned long long r;
    asm("mov.b64 %0, {%1, %1};" : "=l"(r) : "f"(x));
    return r;
}
__device__ __forceinline__ void ffma2(unsigned long long& acc,
                                      unsigned long long a, unsigned long long b) {
    asm("fma.rn.f32x2 %0, %1, %2, %0;" : "+l"(acc) : "l"(a), "l"(b));
}

// ---------------- init / histogram / CSR fill -------------------------------

__global__ void k_init(int n4) {   // n4 = NN/4
    int i = blockIdx.x * blockDim.x + threadIdx.x;
    if (i < n4) {
        ((int4*)g_cnt)[i] = make_int4(0, 0, 0, 0);
        ((int4*)g_cur)[i] = make_int4(0, 0, 0, 0);
    }
}

// histogram over dst half of edge_index (int32), vectorized
__global__ void k_hist(const int* __restrict__ ei, int e) {
    int i = blockIdx.x * blockDim.x + threadIdx.x;   // i over e/4
    if (i >= (e >> 2)) return;
    int4 d = ((const int4*)(ei + e))[i];
    atomicAdd(&g_cnt[d.x], 1);
    atomicAdd(&g_cnt[d.y], 1);
    atomicAdd(&g_cnt[d.z], 1);
    atomicAdd(&g_cnt[d.w], 1);
}

// ---------------- two-level exclusive scan of g_cnt -> g_rowstart -----------

__global__ void k_scan_a(int n) {
    __shared__ int s[SCAN_BLK];
    int t = threadIdx.x;
    int i = blockIdx.x * SCAN_BLK + t;
    int v = (i < n) ? g_cnt[i] : 0;
    s[t] = v;
    __syncthreads();
    #pragma unroll
    for (int off = 1; off < SCAN_BLK; off <<= 1) {
        int tv = (t >= off) ? s[t - off] : 0;
        __syncthreads();
        s[t] += tv;
        __syncthreads();
    }
    if (i < n) g_scan[i] = s[t];
    if (t == SCAN_BLK - 1) g_bsum[blockIdx.x] = s[t];
}

__global__ void k_scan_b(int nb) {
    __shared__ int s[SCAN_BLK];
    int t = threadIdx.x;
    int v = (t < nb) ? g_bsum[t] : 0;
    s[t] = v;
    __syncthreads();
    #pragma unroll
    for (int off = 1; off < SCAN_BLK; off <<= 1) {
        int tv = (t >= off) ? s[t - off] : 0;
        __syncthreads();
        s[t] += tv;
        __syncthreads();
    }
    if (t < nb) g_boff[t] = s[t] - v;   // exclusive
}

__global__ void k_scan_c(int n, int e) {
    int i = blockIdx.x * blockDim.x + threadIdx.x;
    if (i < n) {
        int cnt = g_cnt[i];
        g_rowstart[i] = g_scan[i] - cnt + g_boff[i / SCAN_BLK];  // exclusive
        g_dinv[i] = rsqrtf((float)(cnt + 1));                    // +1 self loop
    }
    if (i == 0) g_rowstart[n] = e;
}

// CSR fill, reading edge_index directly (no src/dst staging)
__global__ void k_fill(const int* __restrict__ ei, int e) {
    int i = blockIdx.x * blockDim.x + threadIdx.x;   // i over e/4
    if (i >= (e >> 2)) return;
    int4 s = ((const int4*)ei)[i];
    int4 d = ((const int4*)(ei + e))[i];
    int p0 = g_rowstart[d.x] + atomicAdd(&g_cur[d.x], 1);
    int p1 = g_rowstart[d.y] + atomicAdd(&g_cur[d.y], 1);
    int p2 = g_rowstart[d.z] + atomicAdd(&g_cur[d.z], 1);
    int p3 = g_rowstart[d.w] + atomicAdd(&g_cur[d.w], 1);
    g_eidx[p0] = s.x;
    g_eidx[p1] = s.y;
    g_eidx[p2] = s.z;
    g_eidx[p3] = s.w;
}

// ---------------- GEMM1: g_A = (x @ W1) * dinv[row]  (packed f32x2) ---------
// 128 threads/block, tile 64 rows x 32 cols, K=128.
// Per thread: 2 rows (tr, tr+32) x 8 cols (8*tc..8*tc+7) as 4 packed accs/row.

__global__ void k_gemm1(const float* __restrict__ x, const float* __restrict__ W1, int n) {
    __shared__ __align__(16) float ws[IN_DIM * H1];   // 16 KB
    __shared__ __align__(16) float xs[64 * 132];      // padded rows
    const int t = threadIdx.x;
    const int row0 = blockIdx.x * 64;

    {   // W1: 128x32 = 1024 float4
        const float4* w4 = (const float4*)W1;
        float4* s4 = (float4*)ws;
        #pragma unroll
        for (int i = t; i < 1024; i += 128) s4[i] = w4[i];
    }
    {   // x tile: 64 rows x 32 float4
        const float4* x4 = (const float4*)x;
        #pragma unroll
        for (int i = t; i < 2048; i += 128) {
            int r = i >> 5, c = i & 31;
            float4 v = make_float4(0.f, 0.f, 0.f, 0.f);
            if (row0 + r < n) v = x4[(size_t)(row0 + r) * 32 + c];
            *(float4*)(&xs[r * 132 + c * 4]) = v;
        }
    }
    __syncthreads();

    const int tc = t & 3;    // col group: cols 8*tc..8*tc+7
    const int tr = t >> 2;   // rows tr, tr+32
    unsigned long long acc0[4] = {0ull, 0ull, 0ull, 0ull};
    unsigned long long acc1[4] = {0ull, 0ull, 0ull, 0ull};
    const float* xpa = &xs[tr * 132];
    const float* xpb = &xs[(tr + 32) * 132];
    const ulonglong2* wp = (const ulonglong2*)ws;   // row k: 8 ulonglong2

    #pragma unroll 4
    for (int k = 0; k < IN_DIM; k++) {
        unsigned long long xa2 = pack_dup(xpa[k]);
        unsigned long long xb2 = pack_dup(xpb[k]);
        ulonglong2 wA = wp[k * 8 + tc * 2];       // cols 8tc..8tc+3
        ulonglong2 wB = wp[k * 8 + tc * 2 + 1];   // cols 8tc+4..8tc+7
        ffma2(acc0[0], xa2, wA.x); ffma2(acc0[1], xa2, wA.y);
        ffma2(acc0[2], xa2, wB.x); ffma2(acc0[3], xa2, wB.y);
        ffma2(acc1[0], xb2, wA.x); ffma2(acc1[1], xb2, wA.y);
        ffma2(acc1[2], xb2, wB.x); ffma2(acc1[3], xb2, wB.y);
    }

    float4* A4 = (float4*)g_A;
    int r0 = row0 + tr;
    if (r0 < n) {
        float dv = g_dinv[r0];
        F2U u0, u1, u2, u3;
        u0.u = acc0[0]; u1.u = acc0[1]; u2.u = acc0[2]; u3.u = acc0[3];
        A4[(size_t)r0 * 8 + tc * 2] =
            make_float4(u0.f.x * dv, u0.f.y * dv, u1.f.x * dv, u1.f.y * dv);
        A4[(size_t)r0 * 8 + tc * 2 + 1] =
            make_float4(u2.f.x * dv, u2.f.y * dv, u3.f.x * dv, u3.f.y * dv);
    }
    int r1 = row0 + tr + 32;
    if (r1 < n) {
        float dv = g_dinv[r1];
        F2U u0, u1, u2, u3;
        u0.u = acc1[0]; u1.u = acc1[1]; u2.u = acc1[2]; u3.u = acc1[3];
        A4[(size_t)r1 * 8 + tc * 2] =
            make_float4(u0.f.x * dv, u0.f.y * dv, u1.f.x * dv, u1.f.y * dv);
        A4[(size_t)r1 * 8 + tc * 2 + 1] =
            make_float4(u2.f.x * dv, u2.f.y * dv, u3.f.x * dv, u3.f.y * dv);
    }
}

// ---------------- gather1: h1 = relu((y1[node] + sum y1[nbr]) * dinv + b1) --
// warp per node, lane = channel (H1 = 32). Index list read via int4 broadcast.

__global__ void k_gather1(const float* __restrict__ b1, int n) {
    int node = blockIdx.x * (blockDim.x >> 5) + (threadIdx.x >> 5);
    if (node >= n) return;
    int lane = threadIdx.x & 31;
    int beg = g_rowstart[node], end = g_rowstart[node + 1];

    float a0 = g_A[(size_t)node * H1 + lane];   // self loop
    float a1 = 0.f, a2 = 0.f, a3 = 0.f;
    int j = beg;
    // align j to 4 (warp-uniform loop, <=3 iters)
    while (j < end && (j & 3)) { a0 += g_A[(size_t)g_eidx[j] * H1 + lane]; j++; }
    for (; j + 4 <= end; j += 4) {
        int4 s = *(const int4*)&g_eidx[j];
        a0 += g_A[(size_t)s.x * H1 + lane];
        a1 += g_A[(size_t)s.y * H1 + lane];
        a2 += g_A[(size_t)s.z * H1 + lane];
        a3 += g_A[(size_t)s.w * H1 + lane];
    }
    for (; j < end; j++) a0 += g_A[(size_t)g_eidx[j] * H1 + lane];

    float acc = (a0 + a1) + (a2 + a3);
    float dv = g_dinv[node];
    g_B[(size_t)node * H1 + lane] = fmaxf(acc * dv + b1[lane], 0.f);
}

// ---------------- GEMM2: g_C = (h1 @ W2) * dinv  (thread per node) ----------

__global__ void k_gemm2(const float* __restrict__ W2, int n) {
    __shared__ float w2s[H1 * H2];
    int t = threadIdx.x;
    for (int i = t; i < H1 * H2; i += blockDim.x) w2s[i] = W2[i];
    __syncthreads();

    int node = blockIdx.x * blockDim.x + t;
    if (node >= n) return;

    float h[H1];
    {
        const float4* a4 = (const float4*)g_B;
        #pragma unroll
        for (int q = 0; q < 8; q++) {
            float4 v = a4[(size_t)node * 8 + q];
            h[q * 4 + 0] = v.x; h[q * 4 + 1] = v.y; h[q * 4 + 2] = v.z; h[q * 4 + 3] = v.w;
        }
    }
    float acc[H2];
    #pragma unroll
    for (int jj = 0; jj < H2; jj++) acc[jj] = 0.f;
    #pragma unroll
    for (int k = 0; k < H1; k++) {
        float hk = h[k];
        #pragma unroll
        for (int jj = 0; jj < 4; jj++) {
            float4 w = *(const float4*)(&w2s[k * H2 + jj * 4]);
            acc[jj * 4 + 0] += hk * w.x;
            acc[jj * 4 + 1] += hk * w.y;
            acc[jj * 4 + 2] += hk * w.z;
            acc[jj * 4 + 3] += hk * w.w;
        }
    }
    float dv = g_dinv[node];
    float4* C4 = (float4*)g_C;
    #pragma unroll
    for (int jj = 0; jj < 4; jj++)
        C4[(size_t)node * 4 + jj] =
            make_float4(acc[jj * 4 + 0] * dv, acc[jj * 4 + 1] * dv,
                        acc[jj * 4 + 2] * dv, acc[jj * 4 + 3] * dv);
}

// ---------------- gather2 + relu + FC + log_softmax -------------------------
// 16 lanes per node (H2 = 16), 2 nodes per warp.

__global__ void k_gather2_final(const float* __restrict__ b2,
                                const float* __restrict__ Wfc,
                                const float* __restrict__ bfc,
                                float* __restrict__ out, int n) {
    int grp  = blockIdx.x * (blockDim.x >> 4) + (threadIdx.x >> 4);
    int lane = threadIdx.x & 15;
    bool valid = (grp < n);
    int node = valid ? grp : 0;

    int beg = g_rowstart[node], end = g_rowstart[node + 1];
    if (!valid) { beg = 0; end = 0; }

    float a0 = valid ? g_C[(size_t)node * H2 + lane] : 0.f;
    float a1 = 0.f, a2 = 0.f, a3 = 0.f;
    int j = beg;
    while (j < end && (j & 3)) { a0 += g_C[(size_t)g_eidx[j] * H2 + lane]; j++; }
    for (; j + 4 <= end; j += 4) {
        int4 s = *(const int4*)&g_eidx[j];
        a0 += g_C[(size_t)s.x * H2 + lane];
        a1 += g_C[(size_t)s.y * H2 + lane];
        a2 += g_C[(size_t)s.z * H2 + lane];
        a3 += g_C[(size_t)s.w * H2 + lane];
    }
    for (; j < end; j++) a0 += g_C[(size_t)g_eidx[j] * H2 + lane];
    float acc = (a0 + a1) + (a2 + a3);

    float dv = g_dinv[node];
    float h = fmaxf(acc * dv + b2[lane], 0.f);
    float2 w = ((const float2*)Wfc)[lane];   // Wfc row-major [16,2]
    float p0 = h * w.x;
    float p1 = h * w.y;
    #pragma unroll
    for (int off = 8; off >= 1; off >>= 1) {
        p0 += __shfl_xor_sync(0xffffffffu, p0, off, 16);
        p1 += __shfl_xor_sync(0xffffffffu, p1, off, 16);
    }
    if (valid && lane == 0) {
        float l0 = p0 + bfc[0];
        float l1 = p1 + bfc[1];
        float m = fmaxf(l0, l1);
        float lse = m + logf(expf(l0 - m) + expf(l1 - m));
        ((float2*)out)[node] = make_float2(l0 - lse, l1 - lse);
    }
}

// ---------------- launch -----------------------------------------------------

extern "C" void kernel_launch(void* const* d_in, const int* in_sizes, int n_in,
                              void* d_out, int out_size) {
    const float* x   = (const float*)d_in[0];
    const int*   ei  = (const int*)d_in[1];     // int32 (JAX default x64 off)
    const float* W1  = (const float*)d_in[2];
    const float* b1  = (const float*)d_in[3];
    const float* W2  = (const float*)d_in[4];
    const float* b2  = (const float*)d_in[5];
    const float* Wfc = (const float*)d_in[6];
    const float* bfc = (const float*)d_in[7];
    float* out = (float*)d_out;

    const int n = in_sizes[0] / IN_DIM;   // 500000
    const int e = in_sizes[1] / 2;        // 8000000 (divisible by 4)
    const int nb = (n + SCAN_BLK - 1) / SCAN_BLK;
    const int T = 256;

    k_init<<<(n / 4 + T - 1) / T, T>>>(n / 4);
    k_hist<<<(e / 4 + T - 1) / T, T>>>(ei, e);

    k_scan_a<<<nb, SCAN_BLK>>>(n);
    k_scan_b<<<1, SCAN_BLK>>>(nb);
    k_scan_c<<<(n + T - 1) / T, T>>>(n, e);
    k_fill<<<(e / 4 + T - 1) / T, T>>>(ei, e);

    k_gemm1<<<(n + 63) / 64, 128>>>(x, W1, n);

    k_gather1<<<(n * 32 + T - 1) / T, T>>>(b1, n);

    k_gemm2<<<(n + T - 1) / T, T>>>(W2, n);

    k_gather2_final<<<(n * 16 + T - 1) / T, T>>>(b2, Wfc, bfc, out, n);
}

// round 7
// speedup vs baseline: 1.0701x; 1.0701x over previous
#include <cuda_runtime.h>
#include <cuda_bf16.h>
#include <math.h>

// Problem constants (fixed by the dataset)
#define NN 500000
#define EE 8000000
#define IN_DIM 128
#define H1 32
#define H2 16
#define SCAN_BLK 1024
#define NB_SCAN ((NN + SCAN_BLK - 1) / SCAN_BLK)   // 489

// Scratch (device globals; no cudaMalloc allowed)
__device__ float g_A[NN * H1];        // y1 = (x@W1)*dinv
__device__ float g_C[NN * H2];        // y2 = (h1@W2)*dinv
__device__ int   g_eidx[EE];          // CSR: src ids grouped by dst
__device__ int   g_cnt[NN];           // edge in-degree (no self loop)
__device__ int   g_cur[NN];           // fill cursors
__device__ int   g_scan[NN];          // per-block inclusive scan of cnt
__device__ int   g_bsum[NB_SCAN];     // block totals
__device__ int   g_boff[NB_SCAN];     // exclusive scan of block totals
__device__ int   g_rowstart[NN + 1];
__device__ float g_dinv[NN];

// ---------------- packed f32x2 helpers --------------------------------------

union F2U { unsigned long long u; float2 f; };

__device__ __forceinline__ unsigned long long pack_dup(float x) {
    unsigned long long r;
    asm("mov.b64 %0, {%1, %1};" : "=l"(r) : "f"(x));
    return r;
}
__device__ __forceinline__ void ffma2(unsigned long long& acc,
                                      unsigned long long a, unsigned long long b) {
    asm("fma.rn.f32x2 %0, %1, %2, %0;" : "+l"(acc) : "l"(a), "l"(b));
}

// ---------------- init / histogram / CSR fill -------------------------------

__global__ void k_init(int n4) {   // n4 = NN/4
    int i = blockIdx.x * blockDim.x + threadIdx.x;
    if (i < n4) {
        ((int4*)g_cnt)[i] = make_int4(0, 0, 0, 0);
        ((int4*)g_cur)[i] = make_int4(0, 0, 0, 0);
    }
}

__global__ void k_hist(const int* __restrict__ ei, int e) {
    int i = blockIdx.x * blockDim.x + threadIdx.x;   // over e/4
    if (i >= (e >> 2)) return;
    int4 d = ((const int4*)(ei + e))[i];
    atomicAdd(&g_cnt[d.x], 1);
    atomicAdd(&g_cnt[d.y], 1);
    atomicAdd(&g_cnt[d.z], 1);
    atomicAdd(&g_cnt[d.w], 1);
}

// ---------------- two-level exclusive scan of g_cnt -> g_rowstart -----------

__global__ void k_scan_a(int n) {
    __shared__ int s[SCAN_BLK];
    int t = threadIdx.x;
    int i = blockIdx.x * SCAN_BLK + t;
    int v = (i < n) ? g_cnt[i] : 0;
    s[t] = v;
    __syncthreads();
    #pragma unroll
    for (int off = 1; off < SCAN_BLK; off <<= 1) {
        int tv = (t >= off) ? s[t - off] : 0;
        __syncthreads();
        s[t] += tv;
        __syncthreads();
    }
    if (i < n) g_scan[i] = s[t];
    if (t == SCAN_BLK - 1) g_bsum[blockIdx.x] = s[t];
}

__global__ void k_scan_b(int nb) {
    __shared__ int s[SCAN_BLK];
    int t = threadIdx.x;
    int v = (t < nb) ? g_bsum[t] : 0;
    s[t] = v;
    __syncthreads();
    #pragma unroll
    for (int off = 1; off < SCAN_BLK; off <<= 1) {
        int tv = (t >= off) ? s[t - off] : 0;
        __syncthreads();
        s[t] += tv;
        __syncthreads();
    }
    if (t < nb) g_boff[t] = s[t] - v;   // exclusive
}

__global__ void k_scan_c(int n, int e) {
    int i = blockIdx.x * blockDim.x + threadIdx.x;
    if (i < n) {
        int cnt = g_cnt[i];
        g_rowstart[i] = g_scan[i] - cnt + g_boff[i / SCAN_BLK];  // exclusive
        g_dinv[i] = rsqrtf((float)(cnt + 1));                    // +1 self loop
    }
    if (i == 0) g_rowstart[n] = e;
}

__global__ void k_fill(const int* __restrict__ ei, int e) {
    int i = blockIdx.x * blockDim.x + threadIdx.x;   // over e/4
    if (i >= (e >> 2)) return;
    int4 s = ((const int4*)ei)[i];
    int4 d = ((const int4*)(ei + e))[i];
    int p0 = g_rowstart[d.x] + atomicAdd(&g_cur[d.x], 1);
    int p1 = g_rowstart[d.y] + atomicAdd(&g_cur[d.y], 1);
    int p2 = g_rowstart[d.z] + atomicAdd(&g_cur[d.z], 1);
    int p3 = g_rowstart[d.w] + atomicAdd(&g_cur[d.w], 1);
    g_eidx[p0] = s.x;
    g_eidx[p1] = s.y;
    g_eidx[p2] = s.z;
    g_eidx[p3] = s.w;
}

// ---------------- GEMM1: g_A = (x @ W1) * dinv[row]  ------------------------
// Thread per row. W1 (128x32) staged in smem, broadcast LDS.128 reads.
// Per k: 8 LDS.128 (broadcast) + 16 FFMA2 -> fma-pipe bound.

__global__ void k_gemm1(const float* __restrict__ x, const float* __restrict__ W1, int n) {
    __shared__ __align__(16) float ws[IN_DIM * H1];   // 16 KB
    const int t = threadIdx.x;
    {
        const float4* w4 = (const float4*)W1;
        float4* s4 = (float4*)ws;
        #pragma unroll
        for (int i = t; i < 1024; i += 256) s4[i] = w4[i];
    }
    __syncthreads();

    int row = blockIdx.x * 256 + t;
    if (row >= n) return;

    unsigned long long acc[16];
    #pragma unroll
    for (int c = 0; c < 16; c++) acc[c] = 0ull;

    const float4* xr = (const float4*)(x + (size_t)row * IN_DIM);   // 32 float4
    #pragma unroll 2
    for (int k4 = 0; k4 < 32; k4++) {
        float4 xv = xr[k4];
        #pragma unroll
        for (int u = 0; u < 4; u++) {
            float xs = (u == 0) ? xv.x : (u == 1) ? xv.y : (u == 2) ? xv.z : xv.w;
            unsigned long long xx = pack_dup(xs);
            const ulonglong2* wr = (const ulonglong2*)&ws[(k4 * 4 + u) * H1];
            #pragma unroll
            for (int c4 = 0; c4 < 8; c4++) {
                ulonglong2 w2 = wr[c4];
                ffma2(acc[c4 * 2], xx, w2.x);
                ffma2(acc[c4 * 2 + 1], xx, w2.y);
            }
        }
    }

    float dv = g_dinv[row];
    float4* A4 = (float4*)(g_A + (size_t)row * H1);
    #pragma unroll
    for (int q = 0; q < 8; q++) {
        F2U a, b;
        a.u = acc[q * 2]; b.u = acc[q * 2 + 1];
        A4[q] = make_float4(a.f.x * dv, a.f.y * dv, b.f.x * dv, b.f.y * dv);
    }
}

// ---------------- layer1 fused: gather1 + relu + GEMM2 ----------------------
// Warp per node. Edge rows (128B) loaded 4-edges-per-warp-LDG:
//   lane l: g = l>>3 selects edge within quad, sub = l&7 selects 16B chunk.
// Then h1 kept in per-warp smem; y2 = (h1@W2)*dinv computed warp-locally.

__global__ void k_layer1(const float* __restrict__ b1, const float* __restrict__ W2, int n) {
    __shared__ float w2s[H1 * 17];          // padded: W2[k][j] at k*17+j
    __shared__ float h1s[8][H1];            // per-warp h1 buffer
    const int t = threadIdx.x;
    for (int i = t; i < H1 * H2; i += 256) {
        w2s[(i >> 4) * 17 + (i & 15)] = W2[i];
    }
    __syncthreads();

    int wid = t >> 5;
    int node = blockIdx.x * 8 + wid;
    if (node >= n) return;
    int lane = t & 31;
    int g = lane >> 3;       // 0..3  edge-in-quad
    int sub = lane & 7;      // 0..7  16B chunk of the 128B row

    int beg = g_rowstart[node], end = g_rowstart[node + 1];
    float4 acc = make_float4(0.f, 0.f, 0.f, 0.f);

    int j = beg & ~3;
    // 2 quads per iteration for MLP
    for (; j + 4 < end; j += 8) {
        int i0 = j + g;
        int i1 = j + 4 + g;
        int s0 = g_eidx[i0];
        int s1 = (i1 < EE) ? g_eidx[i1] : 0;
        bool a0 = (i0 >= beg) & (i0 < end);
        bool a1 = (i1 >= beg) & (i1 < end);
        if (a0) {
            float4 v = *(const float4*)&g_A[(size_t)s0 * H1 + sub * 4];
            acc.x += v.x; acc.y += v.y; acc.z += v.z; acc.w += v.w;
        }
        if (a1) {
            float4 v = *(const float4*)&g_A[(size_t)s1 * H1 + sub * 4];
            acc.x += v.x; acc.y += v.y; acc.z += v.z; acc.w += v.w;
        }
    }
    if (j < end) {           // last quad
        int i0 = j + g;
        int s0 = g_eidx[i0];
        if (i0 >= beg && i0 < end) {
            float4 v = *(const float4*)&g_A[(size_t)s0 * H1 + sub * 4];
            acc.x += v.x; acc.y += v.y; acc.z += v.z; acc.w += v.w;
        }
    }

    // reduce over the 4 edge groups (lanes differing in bits 3,4)
    #pragma unroll
    for (int off = 8; off <= 16; off <<= 1) {
        acc.x += __shfl_xor_sync(0xffffffffu, acc.x, off);
        acc.y += __shfl_xor_sync(0xffffffffu, acc.y, off);
        acc.z += __shfl_xor_sync(0xffffffffu, acc.z, off);
        acc.w += __shfl_xor_sync(0xffffffffu, acc.w, off);
    }

    // self loop + norm + bias + relu
    float dv = g_dinv[node];
    float4 self = *(const float4*)&g_A[(size_t)node * H1 + sub * 4];
    float4 bb = *(const float4*)&b1[sub * 4];
    float4 h;
    h.x = fmaxf((acc.x + self.x) * dv + bb.x, 0.f);
    h.y = fmaxf((acc.y + self.y) * dv + bb.y, 0.f);
    h.z = fmaxf((acc.z + self.z) * dv + bb.z, 0.f);
    h.w = fmaxf((acc.w + self.w) * dv + bb.w, 0.f);

    if (g == 0) *(float4*)&h1s[wid][sub * 4] = h;
    __syncwarp();

    // GEMM2: y2[jj] = dinv * sum_k h1[k] * W2[k][jj]
    int half = lane >> 4;    // 0/1: k range
    int jj = lane & 15;
    float acc2 = 0.f;
    #pragma unroll
    for (int i = 0; i < 16; i++) {
        int k = half * 16 + i;
        acc2 += h1s[wid][k] * w2s[k * 17 + jj];
    }
    acc2 += __shfl_xor_sync(0xffffffffu, acc2, 16);
    if (half == 0) g_C[(size_t)node * H2 + jj] = acc2 * dv;
}

// ---------------- layer2 fused: gather2 + relu + FC + log_softmax -----------
// Warp per node. Edge rows (64B) loaded 8-edges-per-warp-LDG:
//   lane l: g = l>>2 edge-in-octet, sub = l&3 16B chunk of the 64B row.

__global__ void k_layer2(const float* __restrict__ b2,
                         const float* __restrict__ Wfc,
                         const float* __restrict__ bfc,
                         float* __restrict__ out, int n) {
    int t = threadIdx.x;
    int wid = t >> 5;
    int node = blockIdx.x * 8 + wid;
    if (node >= n) return;
    int lane = t & 31;
    int g = lane >> 2;       // 0..7
    int sub = lane & 3;      // 0..3

    int beg = g_rowstart[node], end = g_rowstart[node + 1];
    float4 acc = make_float4(0.f, 0.f, 0.f, 0.f);

    int j = beg & ~7;
    for (; j + 8 < end; j += 16) {
        int i0 = j + g;
        int i1 = j + 8 + g;
        int s0 = g_eidx[i0];
        int s1 = (i1 < EE) ? g_eidx[i1] : 0;
        if (i0 >= beg && i0 < end) {
            float4 v = *(const float4*)&g_C[(size_t)s0 * H2 + sub * 4];
            acc.x += v.x; acc.y += v.y; acc.z += v.z; acc.w += v.w;
        }
        if (i1 >= beg && i1 < end) {
            float4 v = *(const float4*)&g_C[(size_t)s1 * H2 + sub * 4];
            acc.x += v.x; acc.y += v.y; acc.z += v.z; acc.w += v.w;
        }
    }
    if (j < end) {
        int i0 = j + g;
        int s0 = g_eidx[i0];
        if (i0 >= beg && i0 < end) {
            float4 v = *(const float4*)&g_C[(size_t)s0 * H2 + sub * 4];
            acc.x += v.x; acc.y += v.y; acc.z += v.z; acc.w += v.w;
        }
    }

    // reduce over the 8 edge groups (lanes differing in bits 2,3,4)
    #pragma unroll
    for (int off = 4; off <= 16; off <<= 1) {
        acc.x += __shfl_xor_sync(0xffffffffu, acc.x, off);
        acc.y += __shfl_xor_sync(0xffffffffu, acc.y, off);
        acc.z += __shfl_xor_sync(0xffffffffu, acc.z, off);
        acc.w += __shfl_xor_sync(0xffffffffu, acc.w, off);
    }

    float dv = g_dinv[node];
    float4 self = *(const float4*)&g_C[(size_t)node * H2 + sub * 4];
    float4 bb = *(const float4*)&b2[sub * 4];
    float4 h;
    h.x = fmaxf((acc.x + self.x) * dv + bb.x, 0.f);
    h.y = fmaxf((acc.y + self.y) * dv + bb.y, 0.f);
    h.z = fmaxf((acc.z + self.z) * dv + bb.z, 0.f);
    h.w = fmaxf((acc.w + self.w) * dv + bb.w, 0.f);

    // FC: Wfc row-major [16,2]; lane covers channels sub*4..sub*4+3
    const float4* wf = (const float4*)Wfc;
    float4 f0 = wf[sub * 2];       // {W[4s][0],W[4s][1],W[4s+1][0],W[4s+1][1]}
    float4 f1 = wf[sub * 2 + 1];
    float p0 = h.x * f0.x + h.y * f0.z + h.z * f1.x + h.w * f1.z;
    float p1 = h.x * f0.y + h.y * f0.w + h.z * f1.y + h.w * f1.w;
    p0 += __shfl_xor_sync(0xffffffffu, p0, 1);
    p1 += __shfl_xor_sync(0xffffffffu, p1, 1);
    p0 += __shfl_xor_sync(0xffffffffu, p0, 2);
    p1 += __shfl_xor_sync(0xffffffffu, p1, 2);

    if (lane == 0) {
        float l0 = p0 + bfc[0];
        float l1 = p1 + bfc[1];
        float m = fmaxf(l0, l1);
        float lse = m + logf(expf(l0 - m) + expf(l1 - m));
        ((float2*)out)[node] = make_float2(l0 - lse, l1 - lse);
    }
}

// ---------------- launch -----------------------------------------------------

extern "C" void kernel_launch(void* const* d_in, const int* in_sizes, int n_in,
                              void* d_out, int out_size) {
    const float* x   = (const float*)d_in[0];
    const int*   ei  = (const int*)d_in[1];     // int32 (JAX default x64 off)
    const float* W1  = (const float*)d_in[2];
    const float* b1  = (const float*)d_in[3];
    const float* W2  = (const float*)d_in[4];
    const float* b2  = (const float*)d_in[5];
    const float* Wfc = (const float*)d_in[6];
    const float* bfc = (const float*)d_in[7];
    float* out = (float*)d_out;

    const int n = in_sizes[0] / IN_DIM;   // 500000
    const int e = in_sizes[1] / 2;        // 8000000 (divisible by 8)
    const int nb = (n + SCAN_BLK - 1) / SCAN_BLK;
    const int T = 256;

    k_init<<<(n / 4 + T - 1) / T, T>>>(n / 4);
    k_hist<<<(e / 4 + T - 1) / T, T>>>(ei, e);

    k_scan_a<<<nb, SCAN_BLK>>>(n);
    k_scan_b<<<1, SCAN_BLK>>>(nb);
    k_scan_c<<<(n + T - 1) / T, T>>>(n, e);
    k_fill<<<(e / 4 + T - 1) / T, T>>>(ei, e);

    k_gemm1<<<(n + 255) / 256, 256>>>(x, W1, n);

    k_layer1<<<(n + 7) / 8, 256>>>(b1, W2, n);

    k_layer2<<<(n + 7) / 8, 256>>>(b2, Wfc, bfc, out, n);
}

// round 8
// speedup vs baseline: 1.0760x; 1.0055x over previous
#include <cuda_runtime.h>
#include <cuda_bf16.h>
#include <math.h>

// Problem constants (fixed by the dataset)
#define NN 500000
#define EE 8000000
#define IN_DIM 128
#define H1 32
#define H2 16
#define SCAN_BLK 1024
#define NB_SCAN ((NN + SCAN_BLK - 1) / SCAN_BLK)   // 489

// Scratch (device globals; no cudaMalloc allowed)
__device__ float g_A[NN * H1];        // y1 = (x@W1)*dinv
__device__ float g_C[NN * H2];        // y2 = (h1@W2)*dinv
__device__ int   g_eidx[EE];          // CSR: src ids grouped by dst
__device__ int   g_cnt[NN];           // edge in-degree (no self loop)
__device__ int   g_cur[NN];           // fill cursors
__device__ int   g_scan[NN];          // per-block inclusive scan of cnt
__device__ int   g_bsum[NB_SCAN];     // block totals
__device__ int   g_boff[NB_SCAN];     // exclusive scan of block totals
__device__ int   g_rowstart[NN + 1];
__device__ float g_dinv[NN];

// ---------------- packed f32x2 helpers --------------------------------------

union F2U { unsigned long long u; float2 f; };

__device__ __forceinline__ unsigned long long pack_dup(float x) {
    unsigned long long r;
    asm("mov.b64 %0, {%1, %1};" : "=l"(r) : "f"(x));
    return r;
}
__device__ __forceinline__ void ffma2(unsigned long long& acc,
                                      unsigned long long a, unsigned long long b) {
    asm("fma.rn.f32x2 %0, %1, %2, %0;" : "+l"(acc) : "l"(a), "l"(b));
}

// ---------------- init / histogram / CSR fill -------------------------------

__global__ void k_init(int n4) {   // n4 = NN/4
    int i = blockIdx.x * blockDim.x + threadIdx.x;
    if (i < n4) {
        ((int4*)g_cnt)[i] = make_int4(0, 0, 0, 0);
        ((int4*)g_cur)[i] = make_int4(0, 0, 0, 0);
    }
}

__global__ void k_hist(const int* __restrict__ ei, int e) {
    int i = blockIdx.x * blockDim.x + threadIdx.x;   // over e/4
    if (i >= (e >> 2)) return;
    int4 d = ((const int4*)(ei + e))[i];
    atomicAdd(&g_cnt[d.x], 1);
    atomicAdd(&g_cnt[d.y], 1);
    atomicAdd(&g_cnt[d.z], 1);
    atomicAdd(&g_cnt[d.w], 1);
}

// ---------------- two-level exclusive scan of g_cnt -> g_rowstart -----------

__global__ void k_scan_a(int n) {
    __shared__ int s[SCAN_BLK];
    int t = threadIdx.x;
    int i = blockIdx.x * SCAN_BLK + t;
    int v = (i < n) ? g_cnt[i] : 0;
    s[t] = v;
    __syncthreads();
    #pragma unroll
    for (int off = 1; off < SCAN_BLK; off <<= 1) {
        int tv = (t >= off) ? s[t - off] : 0;
        __syncthreads();
        s[t] += tv;
        __syncthreads();
    }
    if (i < n) g_scan[i] = s[t];
    if (t == SCAN_BLK - 1) g_bsum[blockIdx.x] = s[t];
}

__global__ void k_scan_b(int nb) {
    __shared__ int s[SCAN_BLK];
    int t = threadIdx.x;
    int v = (t < nb) ? g_bsum[t] : 0;
    s[t] = v;
    __syncthreads();
    #pragma unroll
    for (int off = 1; off < SCAN_BLK; off <<= 1) {
        int tv = (t >= off) ? s[t - off] : 0;
        __syncthreads();
        s[t] += tv;
        __syncthreads();
    }
    if (t < nb) g_boff[t] = s[t] - v;   // exclusive
}

__global__ void k_scan_c(int n, int e) {
    int i = blockIdx.x * blockDim.x + threadIdx.x;
    if (i < n) {
        int cnt = g_cnt[i];
        g_rowstart[i] = g_scan[i] - cnt + g_boff[i / SCAN_BLK];  // exclusive
        g_dinv[i] = rsqrtf((float)(cnt + 1));                    // +1 self loop
    }
    if (i == 0) g_rowstart[n] = e;
}

__global__ void k_fill(const int* __restrict__ ei, int e) {
    int i = blockIdx.x * blockDim.x + threadIdx.x;   // over e/4
    if (i >= (e >> 2)) return;
    int4 s = ((const int4*)ei)[i];
    int4 d = ((const int4*)(ei + e))[i];
    int p0 = g_rowstart[d.x] + atomicAdd(&g_cur[d.x], 1);
    int p1 = g_rowstart[d.y] + atomicAdd(&g_cur[d.y], 1);
    int p2 = g_rowstart[d.z] + atomicAdd(&g_cur[d.z], 1);
    int p3 = g_rowstart[d.w] + atomicAdd(&g_cur[d.w], 1);
    g_eidx[p0] = s.x;
    g_eidx[p1] = s.y;
    g_eidx[p2] = s.z;
    g_eidx[p3] = s.w;
}

// ---------------- GEMM1: g_A = (x @ W1) * dinv[row]  ------------------------
// Thread per row, FFMA2, x consumed via register-chunk double buffering:
// 4 chunks of 8 float4; chunk c+1 is in flight while chunk c is computed.
// W1 rows broadcast from smem (LDS.128, conflict-free).

__global__ void __launch_bounds__(256, 2)
k_gemm1(const float* __restrict__ x, const float* __restrict__ W1, int n) {
    __shared__ __align__(16) float ws[IN_DIM * H1];   // 16 KB
    const int t = threadIdx.x;
    {
        const float4* w4 = (const float4*)W1;
        float4* s4 = (float4*)ws;
        #pragma unroll
        for (int i = t; i < 1024; i += 256) s4[i] = w4[i];
    }
    __syncthreads();

    int row = blockIdx.x * 256 + t;
    if (row >= n) return;

    unsigned long long acc[16];
    #pragma unroll
    for (int c = 0; c < 16; c++) acc[c] = 0ull;

    const float4* xr = (const float4*)(x + (size_t)row * IN_DIM);   // 32 float4

    float4 buf[8], nxt[8];
    #pragma unroll
    for (int i = 0; i < 8; i++) buf[i] = xr[i];

    #pragma unroll
    for (int chunk = 0; chunk < 4; chunk++) {
        if (chunk < 3) {
            #pragma unroll
            for (int i = 0; i < 8; i++) nxt[i] = xr[(chunk + 1) * 8 + i];
        }
        #pragma unroll
        for (int i = 0; i < 8; i++) {
            float4 xv = buf[i];
            #pragma unroll
            for (int u = 0; u < 4; u++) {
                float xsc = (u == 0) ? xv.x : (u == 1) ? xv.y : (u == 2) ? xv.z : xv.w;
                unsigned long long xx = pack_dup(xsc);
                int k = (chunk * 8 + i) * 4 + u;
                const ulonglong2* wr = (const ulonglong2*)&ws[k * H1];
                #pragma unroll
                for (int c4 = 0; c4 < 8; c4++) {
                    ulonglong2 w2 = wr[c4];
                    ffma2(acc[c4 * 2], xx, w2.x);
                    ffma2(acc[c4 * 2 + 1], xx, w2.y);
                }
            }
        }
        if (chunk < 3) {
            #pragma unroll
            for (int i = 0; i < 8; i++) buf[i] = nxt[i];
        }
    }

    float dv = g_dinv[row];
    float4* A4 = (float4*)(g_A + (size_t)row * H1);
    #pragma unroll
    for (int q = 0; q < 8; q++) {
        F2U a, b;
        a.u = acc[q * 2]; b.u = acc[q * 2 + 1];
        A4[q] = make_float4(a.f.x * dv, a.f.y * dv, b.f.x * dv, b.f.y * dv);
    }
}

// ---------------- layer1 fused: gather1 + relu + GEMM2 ----------------------
// Warp per node. Edge rows (128B) loaded 4-edges-per-warp-LDG:
//   lane l: g = l>>3 selects edge within quad, sub = l&7 selects 16B chunk.
// Then h1 kept in per-warp smem; y2 = (h1@W2)*dinv computed warp-locally.

__global__ void k_layer1(const float* __restrict__ b1, const float* __restrict__ W2, int n) {
    __shared__ float w2s[H1 * 17];          // padded: W2[k][j] at k*17+j
    __shared__ float h1s[8][H1];            // per-warp h1 buffer
    const int t = threadIdx.x;
    for (int i = t; i < H1 * H2; i += 256) {
        w2s[(i >> 4) * 17 + (i & 15)] = W2[i];
    }
    __syncthreads();

    int wid = t >> 5;
    int node = blockIdx.x * 8 + wid;
    if (node >= n) return;
    int lane = t & 31;
    int g = lane >> 3;       // 0..3  edge-in-quad
    int sub = lane & 7;      // 0..7  16B chunk of the 128B row

    int beg = g_rowstart[node], end = g_rowstart[node + 1];
    float4 acc = make_float4(0.f, 0.f, 0.f, 0.f);

    int j = beg & ~3;
    // 2 quads per iteration for MLP
    for (; j + 4 < end; j += 8) {
        int i0 = j + g;
        int i1 = j + 4 + g;
        int s0 = g_eidx[i0];
        int s1 = (i1 < EE) ? g_eidx[i1] : 0;
        bool a0 = (i0 >= beg) & (i0 < end);
        bool a1 = (i1 >= beg) & (i1 < end);
        if (a0) {
            float4 v = *(const float4*)&g_A[(size_t)s0 * H1 + sub * 4];
            acc.x += v.x; acc.y += v.y; acc.z += v.z; acc.w += v.w;
        }
        if (a1) {
            float4 v = *(const float4*)&g_A[(size_t)s1 * H1 + sub * 4];
            acc.x += v.x; acc.y += v.y; acc.z += v.z; acc.w += v.w;
        }
    }
    if (j < end) {           // last quad
        int i0 = j + g;
        int s0 = g_eidx[i0];
        if (i0 >= beg && i0 < end) {
            float4 v = *(const float4*)&g_A[(size_t)s0 * H1 + sub * 4];
            acc.x += v.x; acc.y += v.y; acc.z += v.z; acc.w += v.w;
        }
    }

    // reduce over the 4 edge groups (lanes differing in bits 3,4)
    #pragma unroll
    for (int off = 8; off <= 16; off <<= 1) {
        acc.x += __shfl_xor_sync(0xffffffffu, acc.x, off);
        acc.y += __shfl_xor_sync(0xffffffffu, acc.y, off);
        acc.z += __shfl_xor_sync(0xffffffffu, acc.z, off);
        acc.w += __shfl_xor_sync(0xffffffffu, acc.w, off);
    }

    // self loop + norm + bias + relu
    float dv = g_dinv[node];
    float4 self = *(const float4*)&g_A[(size_t)node * H1 + sub * 4];
    float4 bb = *(const float4*)&b1[sub * 4];
    float4 h;
    h.x = fmaxf((acc.x + self.x) * dv + bb.x, 0.f);
    h.y = fmaxf((acc.y + self.y) * dv + bb.y, 0.f);
    h.z = fmaxf((acc.z + self.z) * dv + bb.z, 0.f);
    h.w = fmaxf((acc.w + self.w) * dv + bb.w, 0.f);

    if (g == 0) *(float4*)&h1s[wid][sub * 4] = h;
    __syncwarp();

    // GEMM2: y2[jj] = dinv * sum_k h1[k] * W2[k][jj]
    int half = lane >> 4;    // 0/1: k range
    int jj = lane & 15;
    float acc2 = 0.f;
    #pragma unroll
    for (int i = 0; i < 16; i++) {
        int k = half * 16 + i;
        acc2 += h1s[wid][k] * w2s[k * 17 + jj];
    }
    acc2 += __shfl_xor_sync(0xffffffffu, acc2, 16);
    if (half == 0) g_C[(size_t)node * H2 + jj] = acc2 * dv;
}

// ---------------- layer2 fused: gather2 + relu + FC + log_softmax -----------
// Warp per node. Edge rows (64B) loaded 8-edges-per-warp-LDG:
//   lane l: g = l>>2 edge-in-octet, sub = l&3 16B chunk of the 64B row.

__global__ void k_layer2(const float* __restrict__ b2,
                         const float* __restrict__ Wfc,
                         const float* __restrict__ bfc,
                         float* __restrict__ out, int n) {
    int t = threadIdx.x;
    int wid = t >> 5;
    int node = blockIdx.x * 8 + wid;
    if (node >= n) return;
    int lane = t & 31;
    int g = lane >> 2;       // 0..7
    int sub = lane & 3;      // 0..3

    int beg = g_rowstart[node], end = g_rowstart[node + 1];
    float4 acc = make_float4(0.f, 0.f, 0.f, 0.f);

    int j = beg & ~7;
    for (; j + 8 < end; j += 16) {
        int i0 = j + g;
        int i1 = j + 8 + g;
        int s0 = g_eidx[i0];
        int s1 = (i1 < EE) ? g_eidx[i1] : 0;
        if (i0 >= beg && i0 < end) {
            float4 v = *(const float4*)&g_C[(size_t)s0 * H2 + sub * 4];
            acc.x += v.x; acc.y += v.y; acc.z += v.z; acc.w += v.w;
        }
        if (i1 >= beg && i1 < end) {
            float4 v = *(const float4*)&g_C[(size_t)s1 * H2 + sub * 4];
            acc.x += v.x; acc.y += v.y; acc.z += v.z; acc.w += v.w;
        }
    }
    if (j < end) {
        int i0 = j + g;
        int s0 = g_eidx[i0];
        if (i0 >= beg && i0 < end) {
            float4 v = *(const float4*)&g_C[(size_t)s0 * H2 + sub * 4];
            acc.x += v.x; acc.y += v.y; acc.z += v.z; acc.w += v.w;
        }
    }

    // reduce over the 8 edge groups (lanes differing in bits 2,3,4)
    #pragma unroll
    for (int off = 4; off <= 16; off <<= 1) {
        acc.x += __shfl_xor_sync(0xffffffffu, acc.x, off);
        acc.y += __shfl_xor_sync(0xffffffffu, acc.y, off);
        acc.z += __shfl_xor_sync(0xffffffffu, acc.z, off);
        acc.w += __shfl_xor_sync(0xffffffffu, acc.w, off);
    }

    float dv = g_dinv[node];
    float4 self = *(const float4*)&g_C[(size_t)node * H2 + sub * 4];
    float4 bb = *(const float4*)&b2[sub * 4];
    float4 h;
    h.x = fmaxf((acc.x + self.x) * dv + bb.x, 0.f);
    h.y = fmaxf((acc.y + self.y) * dv + bb.y, 0.f);
    h.z = fmaxf((acc.z + self.z) * dv + bb.z, 0.f);
    h.w = fmaxf((acc.w + self.w) * dv + bb.w, 0.f);

    // FC: Wfc row-major [16,2]; lane covers channels sub*4..sub*4+3
    const float4* wf = (const float4*)Wfc;
    float4 f0 = wf[sub * 2];       // {W[4s][0],W[4s][1],W[4s+1][0],W[4s+1][1]}
    float4 f1 = wf[sub * 2 + 1];
    float p0 = h.x * f0.x + h.y * f0.z + h.z * f1.x + h.w * f1.z;
    float p1 = h.x * f0.y + h.y * f0.w + h.z * f1.y + h.w * f1.w;
    p0 += __shfl_xor_sync(0xffffffffu, p0, 1);
    p1 += __shfl_xor_sync(0xffffffffu, p1, 1);
    p0 += __shfl_xor_sync(0xffffffffu, p0, 2);
    p1 += __shfl_xor_sync(0xffffffffu, p1, 2);

    if (lane == 0) {
        float l0 = p0 + bfc[0];
        float l1 = p1 + bfc[1];
        float m = fmaxf(l0, l1);
        float lse = m + logf(expf(l0 - m) + expf(l1 - m));
        ((float2*)out)[node] = make_float2(l0 - lse, l1 - lse);
    }
}

// ---------------- launch -----------------------------------------------------

extern "C" void kernel_launch(void* const* d_in, const int* in_sizes, int n_in,
                              void* d_out, int out_size) {
    const float* x   = (const float*)d_in[0];
    const int*   ei  = (const int*)d_in[1];     // int32 (JAX default x64 off)
    const float* W1  = (const float*)d_in[2];
    const float* b1  = (const float*)d_in[3];
    const float* W2  = (const float*)d_in[4];
    const float* b2  = (const float*)d_in[5];
    const float* Wfc = (const float*)d_in[6];
    const float* bfc = (const float*)d_in[7];
    float* out = (float*)d_out;

    const int n = in_sizes[0] / IN_DIM;   // 500000
    const int e = in_sizes[1] / 2;        // 8000000 (divisible by 8)
    const int nb = (n + SCAN_BLK - 1) / SCAN_BLK;
    const int T = 256;

    k_init<<<(n / 4 + T - 1) / T, T>>>(n / 4);
    k_hist<<<(e / 4 + T - 1) / T, T>>>(ei, e);

    k_scan_a<<<nb, SCAN_BLK>>>(n);
    k_scan_b<<<1, SCAN_BLK>>>(nb);
    k_scan_c<<<(n + T - 1) / T, T>>>(n, e);
    k_fill<<<(e / 4 + T - 1) / T, T>>>(ei, e);

    k_gemm1<<<(n + 255) / 256, 256>>>(x, W1, n);

    k_layer1<<<(n + 7) / 8, 256>>>(b1, W2, n);

    k_layer2<<<(n + 7) / 8, 256>>>(b2, Wfc, bfc, out, n);
}